// round 7
// baseline (speedup 1.0000x reference)
#include <cuda_runtime.h>
#include <math.h>

// Prep outputs (written each launch, deterministic)
__device__ __align__(16) float g_qw1t[36];  // conv1 fq weights TRANSPOSED [k][ch]
__device__ __align__(8)  int   g_w2p2[36];  // conv2 packed: [ocp][k][c], byte ci
__device__ int   g_wfp[528];                // FC packed [o][j] byte ci; padded, tail zero
__device__ float g_scales[2];               // {2*s2, 2*sf}

__device__ __forceinline__ int qclip(float w, float s) {
    float r = rintf(w / s);
    r = fminf(fmaxf(r, -1.f), 1.f);
    return (int)r;
}

__global__ void prep_kernel(const float* __restrict__ w1,
                            const float* __restrict__ w2,
                            const float* __restrict__ wf) {
    __shared__ float red[256];
    __shared__ float scales[3];
    int t = threadIdx.x;
    const float* srcs[3] = {w1, w2, wf};
    const int    ns[3]   = {36, 144, 1960};
    for (int j = 0; j < 3; j++) {
        float m = 0.f;
        for (int i = t; i < ns[j]; i += 256) m = fmaxf(m, fabsf(srcs[j][i]));
        red[t] = m;
        __syncthreads();
        for (int s = 128; s > 0; s >>= 1) {
            if (t < s) red[t] = fmaxf(red[t], red[t + s]);
            __syncthreads();
        }
        if (t == 0) scales[j] = red[0];
        __syncthreads();
    }
    float s1 = scales[0], s2 = scales[1], sf = scales[2];

    if (t < 36) {   // conv1 transposed: t = k*4+ch
        int ch = t & 3, k = t >> 2;
        g_qw1t[t] = (float)qclip(w1[ch * 9 + k], s1) * s1;
    }
    if (t < 36) {   // conv2 [ocp][k][c]
        int ocp = t / 18, r = t % 18, k = r >> 1, c = r & 1;
        int oc = 2 * ocp + c;
        int packed = 0;
        #pragma unroll
        for (int ci = 0; ci < 4; ci++) {
            int q = qclip(w2[(oc * 4 + ci) * 9 + k], s2);
            packed |= (q & 0xFF) << (8 * ci);
        }
        g_w2p2[t] = packed;
    }
    for (int i = t; i < 528; i += 256) {
        if (i < 490) {
            int o = i / 49, j = i % 49;
            int packed = 0;
            #pragma unroll
            for (int ci = 0; ci < 4; ci++) {
                int q = qclip(wf[o * 196 + ci * 49 + j], sf);
                packed |= (q & 0xFF) << (8 * ci);
            }
            g_wfp[i] = packed;
        } else {
            g_wfp[i] = 0;
        }
    }
    if (t == 0) { g_scales[0] = 2.f * s2; g_scales[1] = 2.f * sf; }
}

// ---- f32x2 packed helpers ----
typedef unsigned long long ull;
__device__ __forceinline__ ull pk2(float a, float b) {
    ull r; asm("mov.b64 %0, {%1, %2};" : "=l"(r) : "f"(a), "f"(b)); return r;
}
__device__ __forceinline__ ull dup2(float a) {
    ull r; asm("mov.b64 %0, {%1, %1};" : "=l"(r) : "f"(a)); return r;
}
__device__ __forceinline__ void ffma2(ull& d, ull a, ull b) {
    asm("fma.rn.f32x2 %0, %1, %2, %0;" : "+l"(d) : "l"(a), "l"(b));
}
__device__ __forceinline__ void unpk2(ull v, float& lo, float& hi) {
    asm("mov.b64 {%0, %1}, %2;" : "=f"(lo), "=f"(hi) : "l"(v));
}

__device__ __forceinline__ int quant2b(float v) {
    return max(__float2int_rn(fminf(v, 6.f) * 0.5f), 0);
}

// ---------------------------------------------------------------------------
// Warp-per-image fused kernel. Block = 4 independent images, no block syncs.
// ---------------------------------------------------------------------------
__global__ __launch_bounds__(128, 8)
void fused_kernel(const float* __restrict__ x, float* __restrict__ out, int B) {
    __shared__ __align__(16) float s_in[4][900];   // padded 30x30 per image
    __shared__ __align__(16) int   s_p1[4][256];   // padded 16x16 int8x4 acts
    __shared__ __align__(8)  int   s_p2[4][52];    // 7x7 int8x4 acts

    const int t    = threadIdx.x;
    const int lane = t & 31;
    const int w    = t >> 5;
    const int img  = blockIdx.x * 4 + w;
    if (img >= B) return;

    float* my_in = s_in[w];
    int*   my_p1 = s_p1[w];
    int*   my_p2 = s_p2[w];

    // ---- Phase A: zero everything, then load input (float4) ----
    {
        float4 z4 = make_float4(0.f, 0.f, 0.f, 0.f);
        for (int i = lane; i < 225; i += 32) ((float4*)my_in)[i] = z4;
        ((int4*)my_p1)[lane]      = make_int4(0, 0, 0, 0);
        ((int4*)my_p1)[lane + 32] = make_int4(0, 0, 0, 0);
    }
    __syncwarp();
    {
        const float4* xv = (const float4*)(x + (size_t)img * 784);
        for (int idx = lane; idx < 196; idx += 32) {
            float4 v = xv[idx];
            int y = idx / 7, c0 = (idx % 7) * 4;
            float* dst = my_in + (y + 1) * 30 + c0 + 1;
            dst[0] = v.x; dst[1] = v.y; dst[2] = v.z; dst[3] = v.w;
        }
    }
    __syncwarp();

    // ---- Phase B: conv1 + pool + quant. Window-pair f32x2 packing:
    //      acc = (conv@dx0, conv@dx1); act pairs come free from LDS.64
    //      adjacency, weights are dup'd ONCE per pass outside the loop. ----
    #pragma unroll 1
    for (int cp = 0; cp < 2; cp++) {
        ull wd0[9], wd1[9];   // dup'd weights for channels 2cp, 2cp+1
        #pragma unroll
        for (int k = 0; k < 9; k++) {
            float4 v = __ldg((const float4*)g_qw1t + k);
            wd0[k] = dup2(cp ? v.z : v.x);
            wd1[k] = dup2(cp ? v.w : v.y);
        }
        for (int p = lane; p < 196; p += 32) {
            int py = p / 14, px = p - py * 14;
            const float* bp = my_in + py * 60 + px * 2;
            ull a00 = 0, a01 = 0, a10 = 0, a11 = 0;  // acc[ch][dy] = (dx0, dx1)
            #pragma unroll
            for (int row = 0; row < 4; row++) {
                float2 u  = *(const float2*)(bp + 30 * row);
                float2 v2 = *(const float2*)(bp + 30 * row + 2);
                ull pA = pk2(u.x, u.y);    // (c0,c1): aligned pair, ~free
                ull pM = pk2(u.y, v2.x);   // (c1,c2): one real pack
                ull pB = pk2(v2.x, v2.y);  // (c2,c3): aligned pair, ~free
                if (row <= 2) {            // dy=0 window, ky=row
                    ffma2(a00, pA, wd0[row * 3 + 0]);
                    ffma2(a00, pM, wd0[row * 3 + 1]);
                    ffma2(a00, pB, wd0[row * 3 + 2]);
                    ffma2(a10, pA, wd1[row * 3 + 0]);
                    ffma2(a10, pM, wd1[row * 3 + 1]);
                    ffma2(a10, pB, wd1[row * 3 + 2]);
                }
                if (row >= 1) {            // dy=1 window, ky=row-1
                    int kr = row - 1;
                    ffma2(a01, pA, wd0[kr * 3 + 0]);
                    ffma2(a01, pM, wd0[kr * 3 + 1]);
                    ffma2(a01, pB, wd0[kr * 3 + 2]);
                    ffma2(a11, pA, wd1[kr * 3 + 0]);
                    ffma2(a11, pM, wd1[kr * 3 + 1]);
                    ffma2(a11, pB, wd1[kr * 3 + 2]);
                }
            }
            float x0, x1, y0, y1;
            unpk2(a00, x0, x1); unpk2(a01, y0, y1);
            float m0 = fmaxf(fmaxf(x0, x1), fmaxf(y0, y1));
            unpk2(a10, x0, x1); unpk2(a11, y0, y1);
            float m1 = fmaxf(fmaxf(x0, x1), fmaxf(y0, y1));
            int q0 = quant2b(m0), q1 = quant2b(m1);
            ((unsigned short*)my_p1)[((py + 1) * 16 + px + 1) * 2 + cp] =
                (unsigned short)(q0 | (q1 << 8));
        }
    }
    __syncwarp();

    // ---- Phase C: conv2 via dp4a. lane parity = oc-pair (weights hoisted). ----
    {
        const float hs2 = __ldg(&g_scales[0]);
        const int ocp = lane & 1;
        int wq0[9], wq1[9];
        #pragma unroll
        for (int k = 0; k < 9; k++) {
            int2 wv = __ldg((const int2*)(g_w2p2 + ocp * 18) + k);
            wq0[k] = wv.x; wq1[k] = wv.y;
        }
        for (int it = lane; it < 98; it += 32) {
            int pix = it >> 1;
            int py = pix / 7, px = pix - py * 7;
            const int* bp = my_p1 + py * 32 + px * 2;
            int a[16];
            #pragma unroll
            for (int i = 0; i < 4; i++) {
                int2 u = *(const int2*)(bp + 16 * i);
                int2 v = *(const int2*)(bp + 16 * i + 2);
                a[4*i] = u.x; a[4*i+1] = u.y; a[4*i+2] = v.x; a[4*i+3] = v.y;
            }
            int m0 = -1000000, m1 = -1000000;
            #pragma unroll
            for (int dy = 0; dy < 2; dy++) {
                #pragma unroll
                for (int dx = 0; dx < 2; dx++) {
                    int s0a = 0, s0b = 0, s1a = 0, s1b = 0;
                    #pragma unroll
                    for (int ky = 0; ky < 3; ky++) {
                        int av0 = a[(dy + ky) * 4 + dx + 0];
                        int av1 = a[(dy + ky) * 4 + dx + 1];
                        int av2 = a[(dy + ky) * 4 + dx + 2];
                        s0a = __dp4a(av0, wq0[ky * 3 + 0], s0a);
                        s0b = __dp4a(av1, wq0[ky * 3 + 1], s0b);
                        s0a = __dp4a(av2, wq0[ky * 3 + 2], s0a);
                        s1a = __dp4a(av0, wq1[ky * 3 + 0], s1a);
                        s1b = __dp4a(av1, wq1[ky * 3 + 1], s1b);
                        s1a = __dp4a(av2, wq1[ky * 3 + 2], s1a);
                    }
                    m0 = max(m0, s0a + s0b); m1 = max(m1, s1a + s1b);
                }
            }
            int q0 = quant2b(hs2 * (float)m0);
            int q1 = quant2b(hs2 * (float)m1);
            ((unsigned short*)my_p2)[pix * 2 + ocp] =
                (unsigned short)(q0 | (q1 << 8));
        }
    }
    __syncwarp();

    // ---- Phase D: FC 196->10. All partial dp4a first, then independent REDUX. ----
    {
        const float hsf = __ldg(&g_scales[1]);
        int a0 = my_p2[lane];
        int a1 = (lane < 17) ? my_p2[32 + lane] : 0;
        int s[10];
        #pragma unroll
        for (int o = 0; o < 10; o++) {
            const int* wrow = g_wfp + o * 49;
            int v = __dp4a(a0, __ldg(wrow + lane), 0);
            s[o] = __dp4a(a1, __ldg(wrow + 32 + lane), v);  // g_wfp padded: OOB-safe
        }
        float acc = 0.f;
        #pragma unroll
        for (int o = 0; o < 10; o++) {
            int r = __reduce_add_sync(0xffffffffu, s[o]);
            if (lane == o) acc = hsf * (float)r;
        }
        if (lane < 10) out[(size_t)img * 10 + lane] = acc;
    }
}

extern "C" void kernel_launch(void* const* d_in, const int* in_sizes, int n_in,
                              void* d_out, int out_size) {
    const float* x  = (const float*)d_in[0];
    const float* w1 = (const float*)d_in[1];
    const float* w2 = (const float*)d_in[2];
    const float* wf = (const float*)d_in[3];
    float* out = (float*)d_out;
    int B = in_sizes[0] / 784;

    prep_kernel<<<1, 256>>>(w1, w2, wf);
    fused_kernel<<<(B + 3) / 4, 128>>>(x, out, B);
}

// round 11
// speedup vs baseline: 1.1275x; 1.1275x over previous
#include <cuda_runtime.h>
#include <math.h>

// Prep outputs (written each launch, deterministic)
__device__ __align__(16) float g_qw1t[36];  // conv1 fq weights TRANSPOSED [k][ch]
__device__ __align__(8)  int   g_w2p2[36];  // conv2 packed: [ocp][k][c], byte ci
__device__ int   g_wfp[528];                // FC packed [o][j] byte ci; padded, tail zero
__device__ float g_scales[2];               // {2*s2, 2*sf}

__device__ __forceinline__ int qclip(float w, float s) {
    float r = rintf(w / s);
    r = fminf(fmaxf(r, -1.f), 1.f);
    return (int)r;
}

// One barrier: warp-level max reductions + shared atomicMax on positive-float bits.
__global__ void prep_kernel(const float* __restrict__ w1,
                            const float* __restrict__ w2,
                            const float* __restrict__ wf) {
    __shared__ int smax[3];
    int t = threadIdx.x;
    int lane = t & 31, wrp = t >> 5;
    if (t < 3) smax[t] = 0;
    __syncthreads();

    // warp 0 -> w1, warp 1 -> w2, warps 2..7 -> wf
    float m = 0.f;
    int j;
    if (wrp == 0)      { j = 0; for (int i = lane; i < 36;   i += 32)  m = fmaxf(m, fabsf(w1[i])); }
    else if (wrp == 1) { j = 1; for (int i = lane; i < 144;  i += 32)  m = fmaxf(m, fabsf(w2[i])); }
    else               { j = 2; for (int i = (t - 64); i < 1960; i += 192) m = fmaxf(m, fabsf(wf[i])); }
    #pragma unroll
    for (int off = 16; off; off >>= 1)
        m = fmaxf(m, __shfl_xor_sync(0xffffffffu, m, off));
    if (lane == 0) atomicMax(&smax[j], __float_as_int(m));  // all values >= 0
    __syncthreads();

    float s1 = __int_as_float(smax[0]);
    float s2 = __int_as_float(smax[1]);
    float sf = __int_as_float(smax[2]);

    if (t < 36) {   // conv1 transposed: t = k*4+ch
        int ch = t & 3, k = t >> 2;
        g_qw1t[t] = (float)qclip(w1[ch * 9 + k], s1) * s1;
    }
    if (t >= 64 && t < 100) {   // conv2 [ocp][k][c]
        int i = t - 64;
        int ocp = i / 18, r = i % 18, k = r >> 1, c = r & 1;
        int oc = 2 * ocp + c;
        int packed = 0;
        #pragma unroll
        for (int ci = 0; ci < 4; ci++) {
            int q = qclip(w2[(oc * 4 + ci) * 9 + k], s2);
            packed |= (q & 0xFF) << (8 * ci);
        }
        g_w2p2[i] = packed;
    }
    for (int i = t; i < 528; i += 256) {
        if (i < 490) {
            int o = i / 49, jj = i % 49;
            int packed = 0;
            #pragma unroll
            for (int ci = 0; ci < 4; ci++) {
                int q = qclip(wf[o * 196 + ci * 49 + jj], sf);
                packed |= (q & 0xFF) << (8 * ci);
            }
            g_wfp[i] = packed;
        } else {
            g_wfp[i] = 0;
        }
    }
    if (t == 32) { g_scales[0] = 2.f * s2; g_scales[1] = 2.f * sf; }
}

// ---- f32x2 packed helpers ----
typedef unsigned long long ull;
__device__ __forceinline__ ull pk2(float a, float b) {
    ull r; asm("mov.b64 %0, {%1, %2};" : "=l"(r) : "f"(a), "f"(b)); return r;
}
__device__ __forceinline__ ull dup2(float a) {
    ull r; asm("mov.b64 %0, {%1, %1};" : "=l"(r) : "f"(a)); return r;
}
__device__ __forceinline__ void ffma2(ull& d, ull a, ull b) {
    asm("fma.rn.f32x2 %0, %1, %2, %0;" : "+l"(d) : "l"(a), "l"(b));
}
__device__ __forceinline__ void unpk2(ull v, float& lo, float& hi) {
    asm("mov.b64 {%0, %1}, %2;" : "=f"(lo), "=f"(hi) : "l"(v));
}

__device__ __forceinline__ int quant2b(float v) {
    return max(__float2int_rn(fminf(v, 6.f) * 0.5f), 0);
}

// ---------------------------------------------------------------------------
// Warp-per-image fused kernel. Block = 4 independent images, no block syncs.
// ---------------------------------------------------------------------------
__global__ __launch_bounds__(128, 7)
void fused_kernel(const float* __restrict__ x, float* __restrict__ out, int B) {
    __shared__ __align__(16) float s_in[4][900];   // padded 30x30 per image
    __shared__ __align__(16) int   s_p1[4][256];   // padded 16x16 int8x4 acts
    __shared__ __align__(8)  int   s_p2[4][52];    // 7x7 int8x4 acts

    const int t    = threadIdx.x;
    const int lane = t & 31;
    const int w    = t >> 5;
    const int img  = blockIdx.x * 4 + w;
    if (img >= B) return;

    float* my_in = s_in[w];
    int*   my_p1 = s_p1[w];
    int*   my_p2 = s_p2[w];

    // ---- Phase A: zero everything, then load input (float4) ----
    {
        float4 z4 = make_float4(0.f, 0.f, 0.f, 0.f);
        for (int i = lane; i < 225; i += 32) ((float4*)my_in)[i] = z4;
        ((int4*)my_p1)[lane]      = make_int4(0, 0, 0, 0);
        ((int4*)my_p1)[lane + 32] = make_int4(0, 0, 0, 0);
    }
    __syncwarp();
    {
        const float4* xv = (const float4*)(x + (size_t)img * 784);
        for (int idx = lane; idx < 196; idx += 32) {
            float4 v = xv[idx];
            int y = idx / 7, c0 = (idx % 7) * 4;
            float* dst = my_in + (y + 1) * 30 + c0 + 1;
            dst[0] = v.x; dst[1] = v.y; dst[2] = v.z; dst[3] = v.w;
        }
    }
    __syncwarp();

    // ---- Phase B: conv1 + pool + quant, single pass, channel-pair f32x2.
    //      Weight pairs come adjacent from float4 loads (no MOVs);
    //      activation taps dup'd once each, feeding all 4 accumulators. ----
    {
        ull w01[9], w23[9];
        #pragma unroll
        for (int k = 0; k < 9; k++) {
            float4 v = __ldg((const float4*)g_qw1t + k);
            w01[k] = pk2(v.x, v.y);
            w23[k] = pk2(v.z, v.w);
        }
        for (int p = lane; p < 196; p += 32) {
            int py = p / 14, px = p - py * 14;
            const float* bp = my_in + py * 60 + px * 2;
            ull a01[4] = {0, 0, 0, 0};  // windows w=dy*2+dx, (ch0,ch1)
            ull a23[4] = {0, 0, 0, 0};  // (ch2,ch3)
            #pragma unroll
            for (int row = 0; row < 4; row++) {
                float2 u = *(const float2*)(bp + 30 * row);
                float2 v = *(const float2*)(bp + 30 * row + 2);
                ull d0 = dup2(u.x), d1 = dup2(u.y), d2 = dup2(v.x), d3 = dup2(v.y);
                #pragma unroll
                for (int dy = 0; dy < 2; dy++) {
                    int kr = row - dy;
                    if (kr >= 0 && kr <= 2) {
                        ffma2(a01[dy * 2 + 0], d0, w01[kr * 3 + 0]);
                        ffma2(a01[dy * 2 + 0], d1, w01[kr * 3 + 1]);
                        ffma2(a01[dy * 2 + 0], d2, w01[kr * 3 + 2]);
                        ffma2(a01[dy * 2 + 1], d1, w01[kr * 3 + 0]);
                        ffma2(a01[dy * 2 + 1], d2, w01[kr * 3 + 1]);
                        ffma2(a01[dy * 2 + 1], d3, w01[kr * 3 + 2]);
                        ffma2(a23[dy * 2 + 0], d0, w23[kr * 3 + 0]);
                        ffma2(a23[dy * 2 + 0], d1, w23[kr * 3 + 1]);
                        ffma2(a23[dy * 2 + 0], d2, w23[kr * 3 + 2]);
                        ffma2(a23[dy * 2 + 1], d1, w23[kr * 3 + 0]);
                        ffma2(a23[dy * 2 + 1], d2, w23[kr * 3 + 1]);
                        ffma2(a23[dy * 2 + 1], d3, w23[kr * 3 + 2]);
                    }
                }
            }
            float m0 = -1e30f, m1 = -1e30f, m2 = -1e30f, m3 = -1e30f;
            #pragma unroll
            for (int wi = 0; wi < 4; wi++) {
                float c0, c1, c2, c3;
                unpk2(a01[wi], c0, c1);
                unpk2(a23[wi], c2, c3);
                m0 = fmaxf(m0, c0); m1 = fmaxf(m1, c1);
                m2 = fmaxf(m2, c2); m3 = fmaxf(m3, c3);
            }
            int q0 = quant2b(m0), q1 = quant2b(m1),
                q2 = quant2b(m2), q3 = quant2b(m3);
            my_p1[(py + 1) * 16 + px + 1] = q0 | (q1 << 8) | (q2 << 16) | (q3 << 24);
        }
    }
    __syncwarp();

    // ---- Phase C: conv2 via dp4a. lane parity = oc-pair (weights hoisted). ----
    {
        const float hs2 = __ldg(&g_scales[0]);
        const int ocp = lane & 1;
        int wq0[9], wq1[9];
        #pragma unroll
        for (int k = 0; k < 9; k++) {
            int2 wv = __ldg((const int2*)(g_w2p2 + ocp * 18) + k);
            wq0[k] = wv.x; wq1[k] = wv.y;
        }
        for (int it = lane; it < 98; it += 32) {
            int pix = it >> 1;
            int py = pix / 7, px = pix - py * 7;
            const int* bp = my_p1 + py * 32 + px * 2;
            int a[16];
            #pragma unroll
            for (int i = 0; i < 4; i++) {
                int2 u = *(const int2*)(bp + 16 * i);
                int2 v = *(const int2*)(bp + 16 * i + 2);
                a[4*i] = u.x; a[4*i+1] = u.y; a[4*i+2] = v.x; a[4*i+3] = v.y;
            }
            int m0 = -1000000, m1 = -1000000;
            #pragma unroll
            for (int dy = 0; dy < 2; dy++) {
                #pragma unroll
                for (int dx = 0; dx < 2; dx++) {
                    int s0a = 0, s0b = 0, s1a = 0, s1b = 0;
                    #pragma unroll
                    for (int ky = 0; ky < 3; ky++) {
                        int av0 = a[(dy + ky) * 4 + dx + 0];
                        int av1 = a[(dy + ky) * 4 + dx + 1];
                        int av2 = a[(dy + ky) * 4 + dx + 2];
                        s0a = __dp4a(av0, wq0[ky * 3 + 0], s0a);
                        s0b = __dp4a(av1, wq0[ky * 3 + 1], s0b);
                        s0a = __dp4a(av2, wq0[ky * 3 + 2], s0a);
                        s1a = __dp4a(av0, wq1[ky * 3 + 0], s1a);
                        s1b = __dp4a(av1, wq1[ky * 3 + 1], s1b);
                        s1a = __dp4a(av2, wq1[ky * 3 + 2], s1a);
                    }
                    m0 = max(m0, s0a + s0b); m1 = max(m1, s1a + s1b);
                }
            }
            int q0 = quant2b(hs2 * (float)m0);
            int q1 = quant2b(hs2 * (float)m1);
            ((unsigned short*)my_p2)[pix * 2 + ocp] =
                (unsigned short)(q0 | (q1 << 8));
        }
    }
    __syncwarp();

    // ---- Phase D: FC 196->10. All partial dp4a first, then independent REDUX. ----
    {
        const float hsf = __ldg(&g_scales[1]);
        int a0 = my_p2[lane];
        int a1 = (lane < 17) ? my_p2[32 + lane] : 0;
        int s[10];
        #pragma unroll
        for (int o = 0; o < 10; o++) {
            const int* wrow = g_wfp + o * 49;
            int v = __dp4a(a0, __ldg(wrow + lane), 0);
            s[o] = __dp4a(a1, __ldg(wrow + 32 + lane), v);  // g_wfp padded: OOB-safe
        }
        float acc = 0.f;
        #pragma unroll
        for (int o = 0; o < 10; o++) {
            int r = __reduce_add_sync(0xffffffffu, s[o]);
            if (lane == o) acc = hsf * (float)r;
        }
        if (lane < 10) out[(size_t)img * 10 + lane] = acc;
    }
}

extern "C" void kernel_launch(void* const* d_in, const int* in_sizes, int n_in,
                              void* d_out, int out_size) {
    const float* x  = (const float*)d_in[0];
    const float* w1 = (const float*)d_in[1];
    const float* w2 = (const float*)d_in[2];
    const float* wf = (const float*)d_in[3];
    float* out = (float*)d_out;
    int B = in_sizes[0] / 784;

    prep_kernel<<<1, 256>>>(w1, w2, wf);
    fused_kernel<<<(B + 3) / 4, 128>>>(x, out, B);
}